// round 12
// baseline (speedup 1.0000x reference)
#include <cuda_runtime.h>
#include <cstdint>

// out[n] = w_mp * sum_{e : dst[e]==n} ew[e] * x[src[e]]
// x: [N,32] f32, edge_index: [2,E] int32, ew: [E] f32, w_mp: [1] f32
//
// Two-launch pipeline: bucket-permute -> per-node register gather.
// Gather v4: round-8 structure (slot/float4) + register prefetch of records
// (2 ahead) and pipelined row loads. No shfl in the hot path, small body.

#define N_MAX 120000
#define CAP   64          // Poisson(16): P(deg>=64) ~ 1e-19 per node
#define SPILL_MAX 4096

typedef unsigned long long ull;

__device__ int g_cnt[N_MAX];                   // zero-init
__device__ ull g_rec[(size_t)N_MAX * CAP];     // (bits(ew)<<32)|src
__device__ int g_spill_cnt;                    // zero-init
__device__ int g_spill_dst[SPILL_MAX];
__device__ ull g_spill_rec[SPILL_MAX];

// ---------- K1: one-pass bucket permute (2 edges/thread) ----------
__device__ __forceinline__ void permute_one(int s, int d, float w) {
    int pos = atomicAdd(&g_cnt[d], 1);
    ull r = ((ull)__float_as_uint(w) << 32) | (unsigned)s;
    if (pos < CAP) {
        g_rec[(size_t)d * CAP + pos] = r;
    } else {
        int sp = atomicAdd(&g_spill_cnt, 1);
        if (sp < SPILL_MAX) { g_spill_dst[sp] = d; g_spill_rec[sp] = r; }
    }
}

__global__ __launch_bounds__(256)
void k_permute(const int* __restrict__ ei, const float* __restrict__ ew, int E) {
    int t = blockIdx.x * blockDim.x + threadIdx.x;
    int e = t * 2;
    if (e + 1 < E) {
        int2   s2 = __ldg(reinterpret_cast<const int2*>(ei + e));
        int2   d2 = __ldg(reinterpret_cast<const int2*>(ei + E + e));
        float2 w2 = __ldg(reinterpret_cast<const float2*>(ew + e));
        permute_one(s2.x, d2.x, w2.x);
        permute_one(s2.y, d2.y, w2.y);
    } else if (e < E) {
        permute_one(__ldg(&ei[e]), __ldg(&ei[E + e]), __ldg(&ew[e]));
    }
}

// ---------- K2: per-node gather, warp per node; resets counters ----------
__global__ __launch_bounds__(256)
void k_gather(const float* __restrict__ x, const float* __restrict__ w_mp,
              float* __restrict__ out, int n) {
    int node = (blockIdx.x * blockDim.x + threadIdx.x) >> 5;
    if (node >= n) return;
    int lane = threadIdx.x & 31;
    int slot = lane >> 3;   // 4 concurrent edges per warp
    int c    = lane & 7;    // float4 chunk of the 32-float row

    const ull* rec = g_rec + (size_t)node * CAP;

    // Record prefetch issued BEFORE the count load resolves (unconditional;
    // static bucket memory is always readable, garbage never consumed).
    ull r0 = __ldg(&rec[slot]);          // edge at k
    ull r1 = __ldg(&rec[slot + 4]);      // edge at k+4
    int raw_cnt = __ldg(&g_cnt[node]);
    if (lane == 0) g_cnt[node] = 0;      // early reset (graph replay invariant)
    int cnt = raw_cnt > CAP ? CAP : raw_cnt;

    float4 acc = make_float4(0.f, 0.f, 0.f, 0.f);

    int k = slot;
    if (k < cnt) {
        int src0 = (int)(unsigned)r0;
        float4 v0 = __ldg(reinterpret_cast<const float4*>(x + (size_t)src0 * 32) + c);
        while (k + 4 < cnt) {
            // Issue next row load + next record load before consuming v0.
            int src1 = (int)(unsigned)r1;
            float4 v1 = __ldg(reinterpret_cast<const float4*>(x + (size_t)src1 * 32) + c);
            int kp = k + 8;
            ull rn = __ldg(&rec[kp < CAP ? kp : (CAP - 1)]);
            float w = __uint_as_float((unsigned)(r0 >> 32));
            acc.x = fmaf(w, v0.x, acc.x);
            acc.y = fmaf(w, v0.y, acc.y);
            acc.z = fmaf(w, v0.z, acc.z);
            acc.w = fmaf(w, v0.w, acc.w);
            r0 = r1; r1 = rn; v0 = v1; k += 4;
        }
        float w = __uint_as_float((unsigned)(r0 >> 32));
        acc.x = fmaf(w, v0.x, acc.x);
        acc.y = fmaf(w, v0.y, acc.y);
        acc.z = fmaf(w, v0.z, acc.z);
        acc.w = fmaf(w, v0.w, acc.w);
    }

    // Spill path (cold; practically never taken).
    if (raw_cnt > CAP && slot == 0) {
        int spills = g_spill_cnt; if (spills > SPILL_MAX) spills = SPILL_MAX;
        for (int i = 0; i < spills; i++) {
            if (g_spill_dst[i] == node) {
                ull r = g_spill_rec[i];
                float w  = __uint_as_float((unsigned)(r >> 32));
                int  src = (int)(unsigned)r;
                float4 v = __ldg(reinterpret_cast<const float4*>(x + (size_t)src * 32) + c);
                acc.x = fmaf(w, v.x, acc.x);
                acc.y = fmaf(w, v.y, acc.y);
                acc.z = fmaf(w, v.z, acc.z);
                acc.w = fmaf(w, v.w, acc.w);
            }
        }
    }

    // Reduce the 4 edge-slots (lanes c, c+8, c+16, c+24).
    #pragma unroll
    for (int m = 8; m <= 16; m <<= 1) {
        acc.x += __shfl_xor_sync(0xffffffffu, acc.x, m);
        acc.y += __shfl_xor_sync(0xffffffffu, acc.y, m);
        acc.z += __shfl_xor_sync(0xffffffffu, acc.z, m);
        acc.w += __shfl_xor_sync(0xffffffffu, acc.w, m);
    }

    if (slot == 0) {
        float wm = __ldg(w_mp);
        acc.x *= wm; acc.y *= wm; acc.z *= wm; acc.w *= wm;
        reinterpret_cast<float4*>(out + (size_t)node * 32)[c] = acc;
    }
    if (node == 0 && lane == 1) g_spill_cnt = 0;
}

// ---------- Fallback (proven round-4 path) ----------
__global__ void k_zero_out(float4* __restrict__ out, int n4) {
    int i = blockIdx.x * blockDim.x + threadIdx.x;
    if (i < n4) out[i] = make_float4(0.f, 0.f, 0.f, 0.f);
}

__global__ __launch_bounds__(256)
void k_scatter_atomic(const float* __restrict__ x, const int* __restrict__ ei,
                      const float* __restrict__ ew, const float* __restrict__ w_mp,
                      float* __restrict__ out, int E) {
    int tid = blockIdx.x * blockDim.x + threadIdx.x;
    int e = tid >> 3, c = tid & 7;
    if (e >= E) return;
    int s = __ldg(&ei[e]);
    int d = __ldg(&ei[E + e]);
    float w = __ldg(&ew[e]) * __ldg(w_mp);
    float4 v = __ldg(reinterpret_cast<const float4*>(x + (size_t)s * 32) + c);
    v.x *= w; v.y *= w; v.z *= w; v.w *= w;
    float* dst = out + (size_t)d * 32 + c * 4;
    asm volatile("red.global.add.v4.f32 [%0], {%1, %2, %3, %4};"
                 :: "l"(dst), "f"(v.x), "f"(v.y), "f"(v.z), "f"(v.w)
                 : "memory");
}

extern "C" void kernel_launch(void* const* d_in, const int* in_sizes, int n_in,
                              void* d_out, int out_size) {
    const float* x    = (const float*)d_in[0];
    const int*   ei   = (const int*)d_in[1];
    const float* ew   = (const float*)d_in[2];
    const float* w_mp = (const float*)d_in[3];
    float* out = (float*)d_out;

    int E = in_sizes[2];
    int n = out_size / 32;   // nodes

    if (n <= N_MAX) {
        int pt = (E + 1) / 2;                       // 2 edges per thread
        k_permute<<<(pt + 255) / 256, 256>>>(ei, ew, E);
        k_gather<<<(n * 32 + 255) / 256, 256>>>(x, w_mp, out, n);
    } else {
        int n4 = out_size / 4;
        k_zero_out<<<(n4 + 255) / 256, 256>>>((float4*)out, n4);
        long long threads = (long long)E * 8;
        k_scatter_atomic<<<(int)((threads + 255) / 256), 256>>>(x, ei, ew, w_mp, out, E);
    }
}

// round 13
// speedup vs baseline: 1.4526x; 1.4526x over previous
#include <cuda_runtime.h>
#include <cstdint>

// out[n] = w_mp * sum_{e : dst[e]==n} ew[e] * x[src[e]]
// x: [N,32] f32, edge_index: [2,E] int32, ew: [E] f32, w_mp: [1] f32
//
// Two-launch pipeline: bucket-permute -> per-node gather.
// Gather v5: records burst-loaded to shared memory (one L2 round-trip),
// inner loop = LDS + independent row LDGs, unrolled for MLP. No register
// rotation, no shfl in the hot path.

#define N_MAX 120000
#define CAP   64          // Poisson(16): P(deg>=64) ~ 1e-19 per node
#define SPILL_MAX 4096

typedef unsigned long long ull;

__device__ int g_cnt[N_MAX];                   // zero-init
__device__ ull g_rec[(size_t)N_MAX * CAP];     // (bits(ew)<<32)|src
__device__ int g_spill_cnt;                    // zero-init
__device__ int g_spill_dst[SPILL_MAX];
__device__ ull g_spill_rec[SPILL_MAX];

// ---------- K1: one-pass bucket permute (2 edges/thread) ----------
__device__ __forceinline__ void permute_one(int s, int d, float w) {
    int pos = atomicAdd(&g_cnt[d], 1);
    ull r = ((ull)__float_as_uint(w) << 32) | (unsigned)s;
    if (pos < CAP) {
        g_rec[(size_t)d * CAP + pos] = r;
    } else {
        int sp = atomicAdd(&g_spill_cnt, 1);
        if (sp < SPILL_MAX) { g_spill_dst[sp] = d; g_spill_rec[sp] = r; }
    }
}

__global__ __launch_bounds__(256)
void k_permute(const int* __restrict__ ei, const float* __restrict__ ew, int E) {
    int t = blockIdx.x * blockDim.x + threadIdx.x;
    int e = t * 2;
    if (e + 1 < E) {
        int2   s2 = __ldg(reinterpret_cast<const int2*>(ei + e));
        int2   d2 = __ldg(reinterpret_cast<const int2*>(ei + E + e));
        float2 w2 = __ldg(reinterpret_cast<const float2*>(ew + e));
        permute_one(s2.x, d2.x, w2.x);
        permute_one(s2.y, d2.y, w2.y);
    } else if (e < E) {
        permute_one(__ldg(&ei[e]), __ldg(&ei[E + e]), __ldg(&ew[e]));
    }
}

// ---------- K2: per-node gather, warp per node, smem record stage ----------
__global__ __launch_bounds__(256)
void k_gather(const float* __restrict__ x, const float* __restrict__ w_mp,
              float* __restrict__ out, int n) {
    __shared__ ull s_rec[8][CAP];                 // 8 warps x 64 slots = 4KB
    int wrp  = threadIdx.x >> 5;
    int node = (blockIdx.x * blockDim.x + threadIdx.x) >> 5;
    if (node >= n) return;
    int lane = threadIdx.x & 31;
    int slot = lane >> 3;   // 4 concurrent edges per warp
    int c    = lane & 7;    // float4 chunk of the 32-float row

    const ull* rec = g_rec + (size_t)node * CAP;

    // Unconditional burst: both halves of the bucket + the count, all in
    // flight together (static bucket memory is always readable; garbage
    // slots are never consumed).
    ull ra = __ldg(&rec[lane]);
    ull rb = __ldg(&rec[lane + 32]);
    int raw_cnt = __ldg(&g_cnt[node]);

    s_rec[wrp][lane]      = ra;
    s_rec[wrp][lane + 32] = rb;
    if (lane == 0) g_cnt[node] = 0;      // reset invariant for graph replay
    __syncwarp();

    int cnt = raw_cnt > CAP ? CAP : raw_cnt;

    float4 acc = make_float4(0.f, 0.f, 0.f, 0.f);
    #pragma unroll 4
    for (int k = slot; k < cnt; k += 4) {
        ull r = s_rec[wrp][k];                    // LDS broadcast, 29 cyc
        float w  = __uint_as_float((unsigned)(r >> 32));
        int  src = (int)(unsigned)r;
        float4 v = __ldg(reinterpret_cast<const float4*>(x + (size_t)src * 32) + c);
        acc.x = fmaf(w, v.x, acc.x);
        acc.y = fmaf(w, v.y, acc.y);
        acc.z = fmaf(w, v.z, acc.z);
        acc.w = fmaf(w, v.w, acc.w);
    }

    // Spill path (cold; practically never taken).
    if (raw_cnt > CAP && slot == 0) {
        int spills = g_spill_cnt; if (spills > SPILL_MAX) spills = SPILL_MAX;
        for (int i = 0; i < spills; i++) {
            if (g_spill_dst[i] == node) {
                ull r = g_spill_rec[i];
                float w  = __uint_as_float((unsigned)(r >> 32));
                int  src = (int)(unsigned)r;
                float4 v = __ldg(reinterpret_cast<const float4*>(x + (size_t)src * 32) + c);
                acc.x = fmaf(w, v.x, acc.x);
                acc.y = fmaf(w, v.y, acc.y);
                acc.z = fmaf(w, v.z, acc.z);
                acc.w = fmaf(w, v.w, acc.w);
            }
        }
    }

    // Reduce the 4 edge-slots (lanes c, c+8, c+16, c+24).
    #pragma unroll
    for (int m = 8; m <= 16; m <<= 1) {
        acc.x += __shfl_xor_sync(0xffffffffu, acc.x, m);
        acc.y += __shfl_xor_sync(0xffffffffu, acc.y, m);
        acc.z += __shfl_xor_sync(0xffffffffu, acc.z, m);
        acc.w += __shfl_xor_sync(0xffffffffu, acc.w, m);
    }

    if (slot == 0) {
        float wm = __ldg(w_mp);
        acc.x *= wm; acc.y *= wm; acc.z *= wm; acc.w *= wm;
        reinterpret_cast<float4*>(out + (size_t)node * 32)[c] = acc;
    }
    if (node == 0 && lane == 1) g_spill_cnt = 0;
}

// ---------- Fallback (proven round-4 path) ----------
__global__ void k_zero_out(float4* __restrict__ out, int n4) {
    int i = blockIdx.x * blockDim.x + threadIdx.x;
    if (i < n4) out[i] = make_float4(0.f, 0.f, 0.f, 0.f);
}

__global__ __launch_bounds__(256)
void k_scatter_atomic(const float* __restrict__ x, const int* __restrict__ ei,
                      const float* __restrict__ ew, const float* __restrict__ w_mp,
                      float* __restrict__ out, int E) {
    int tid = blockIdx.x * blockDim.x + threadIdx.x;
    int e = tid >> 3, c = tid & 7;
    if (e >= E) return;
    int s = __ldg(&ei[e]);
    int d = __ldg(&ei[E + e]);
    float w = __ldg(&ew[e]) * __ldg(w_mp);
    float4 v = __ldg(reinterpret_cast<const float4*>(x + (size_t)s * 32) + c);
    v.x *= w; v.y *= w; v.z *= w; v.w *= w;
    float* dst = out + (size_t)d * 32 + c * 4;
    asm volatile("red.global.add.v4.f32 [%0], {%1, %2, %3, %4};"
                 :: "l"(dst), "f"(v.x), "f"(v.y), "f"(v.z), "f"(v.w)
                 : "memory");
}

extern "C" void kernel_launch(void* const* d_in, const int* in_sizes, int n_in,
                              void* d_out, int out_size) {
    const float* x    = (const float*)d_in[0];
    const int*   ei   = (const int*)d_in[1];
    const float* ew   = (const float*)d_in[2];
    const float* w_mp = (const float*)d_in[3];
    float* out = (float*)d_out;

    int E = in_sizes[2];
    int n = out_size / 32;   // nodes

    if (n <= N_MAX) {
        int pt = (E + 1) / 2;                       // 2 edges per thread
        k_permute<<<(pt + 255) / 256, 256>>>(ei, ew, E);
        k_gather<<<(n * 32 + 255) / 256, 256>>>(x, w_mp, out, n);
    } else {
        int n4 = out_size / 4;
        k_zero_out<<<(n4 + 255) / 256, 256>>>((float4*)out, n4);
        long long threads = (long long)E * 8;
        k_scatter_atomic<<<(int)((threads + 255) / 256), 256>>>(x, ei, ew, w_mp, out, E);
    }
}